// round 7
// baseline (speedup 1.0000x reference)
#include <cuda_runtime.h>
#include <math.h>

// Problem dims (fixed by the dataset)
#define Bn   4
#define Cn   256
#define HWn  65536
#define Pn   256
#define THRESH_F 0.8f
#define EPSn 1e-5f

typedef unsigned long long ull;

// ---------------------------------------------------------------------------
// Scratch (no cudaMalloc allowed). All state is restored to its initial value
// by the kernels that consume it, so graph replays see identical state.
// 16B alignment is REQUIRED: these are read/written with float4 (LDG.128).
// ---------------------------------------------------------------------------
__device__ __align__(16) int   g_idx[Bn * Pn];
__device__ __align__(16) float g_feat[Bn * Pn * Cn];   // (B, P, C)
__device__ __align__(16) float g_z[Bn * Pn * Cn];      // (B, P, C)
__device__ __align__(16) float g_z2[Bn * Pn * Cn];     // (B, P, C)

__device__ unsigned int g_hist[3][Bn][65536];    // zero at rest
__device__ unsigned int g_coarse[3][Bn][1024];   // zero at rest
__device__ ull g_prefix[Bn];                     // zero at rest
__device__ int g_K[Bn] = {Pn, Pn, Pn, Pn};       // Pn at rest
__device__ int g_candcnt[Bn];                    // zero at rest
__device__ ull g_cand[Bn][Pn];
__device__ unsigned int g_done[3][Bn];           // zero at rest
__device__ unsigned int g_done_c[Bn];            // zero at rest

// ---------------------------------------------------------------------------
// 48-bit composite key: (monotone_float32 << 16) | (0xFFFF - idx)
// ---------------------------------------------------------------------------
__device__ __forceinline__ ull make_key(float e, int i) {
    float v = (e < THRESH_F) ? 0.0f : e;
    unsigned int ub = __float_as_uint(v);
    ub = (ub & 0x80000000u) ? ~ub : (ub | 0x80000000u);
    return ((ull)ub << 16) | (ull)(0xFFFFu - (unsigned int)i);
}

// ---------------------------------------------------------------------------
// SM bulk copy: out <- x  (256 MB). float4 grid-stride.
// ---------------------------------------------------------------------------
__global__ void __launch_bounds__(256)
copy_kernel(const float4* __restrict__ src, float4* __restrict__ dst) {
    const int n4 = Bn * Cn * HWn / 4;
    int i = blockIdx.x * blockDim.x + threadIdx.x;
    const int stride = gridDim.x * blockDim.x;
    for (; i < n4; i += stride) dst[i] = src[i];
}

// ---------------------------------------------------------------------------
// One fused radix pass: histogram (all 64 blocks per batch) + scan (last
// block) + histogram re-zero for the next graph replay.
// grid = (64, Bn), 1024 threads.  pass = 2 (float hi16) .. 0 (inv-index).
// ---------------------------------------------------------------------------
__global__ void __launch_bounds__(1024)
topk_pass(const float* __restrict__ edge, int pass) {
    const int b = blockIdx.y;
    const int t = threadIdx.x;
    const int i = blockIdx.x * 1024 + t;
    const ull key = make_key(edge[(size_t)b * HWn + i], i);

    bool active;
    if (pass == 2) active = true;
    else           active = ((key >> ((pass + 1) * 16)) == g_prefix[b]);

    const unsigned int bin = (unsigned int)((key >> (pass * 16)) & 0xFFFFull);
    const unsigned int amask = __ballot_sync(0xFFFFFFFFu, active);
    if (active) {
        const int lane = t & 31;
        unsigned int peers = __match_any_sync(amask, bin);
        if (lane == __ffs(peers) - 1)
            atomicAdd(&g_hist[pass][b][bin], (unsigned int)__popc(peers));
        unsigned int peersc = __match_any_sync(amask, bin >> 6);
        if (lane == __ffs(peersc) - 1)
            atomicAdd(&g_coarse[pass][b][bin >> 6], (unsigned int)__popc(peersc));
    }

    // Last-block election.
    __threadfence();
    __shared__ bool is_last;
    if (t == 0) {
        const unsigned int prev = atomicAdd(&g_done[pass][b], 1u);
        is_last = (prev == 63u);
    }
    __syncthreads();
    if (!is_last) return;

    // ---- scan: find digit containing rank K (descending) ----
    const int lane = t & 31;
    const int w = t >> 5;

    __shared__ unsigned int warpsum[32];
    __shared__ unsigned int warpsuf[32];
    __shared__ int sh_chunk;
    __shared__ unsigned int sh_krem;
    __shared__ unsigned int bins[64];

    const unsigned int mine = g_coarse[pass][b][t];

    unsigned int suf = mine;
    #pragma unroll
    for (int off = 1; off < 32; off <<= 1) {
        const unsigned int v = __shfl_down_sync(0xFFFFFFFFu, suf, off);
        if (lane + off < 32) suf += v;
    }
    if (lane == 0) warpsum[w] = suf;
    __syncthreads();

    if (w == 0) {
        const unsigned int ws = warpsum[lane];
        unsigned int wsuf = ws;
        #pragma unroll
        for (int off = 1; off < 32; off <<= 1) {
            const unsigned int v = __shfl_down_sync(0xFFFFFFFFu, wsuf, off);
            if (lane + off < 32) wsuf += v;
        }
        warpsuf[lane] = wsuf - ws;
    }
    __syncthreads();

    const unsigned int K = (unsigned int)g_K[b];
    const unsigned int suf_t = suf + warpsuf[w];
    const unsigned int above = suf_t - mine;
    if (suf_t >= K && above < K) {
        sh_chunk = t;
        sh_krem = K - above;
    }
    __syncthreads();

    const int chunk = sh_chunk;
    if (t < 64) bins[t] = g_hist[pass][b][chunk * 64 + t];
    __syncthreads();

    if (w == 0) {
        const unsigned int krem = sh_krem;
        const unsigned int lo = bins[lane];
        const unsigned int hi = bins[lane + 32];

        unsigned int suf_hi = hi;
        #pragma unroll
        for (int off = 1; off < 32; off <<= 1) {
            const unsigned int v = __shfl_down_sync(0xFFFFFFFFu, suf_hi, off);
            if (lane + off < 32) suf_hi += v;
        }
        const unsigned int hi_total = __shfl_sync(0xFFFFFFFFu, suf_hi, 0);

        unsigned int suf_lo = lo;
        #pragma unroll
        for (int off = 1; off < 32; off <<= 1) {
            const unsigned int v = __shfl_down_sync(0xFFFFFFFFu, suf_lo, off);
            if (lane + off < 32) suf_lo += v;
        }
        suf_lo += hi_total;

        { const unsigned int st = suf_hi, ab = st - hi;
          if (st >= krem && ab < krem) {
              g_prefix[b] = (g_prefix[b] << 16) | (ull)(chunk * 64 + 32 + lane);
              g_K[b] = (int)(krem - ab);
          } }
        { const unsigned int st = suf_lo, ab = st - lo;
          if (st >= krem && ab < krem) {
              g_prefix[b] = (g_prefix[b] << 16) | (ull)(chunk * 64 + lane);
              g_K[b] = (int)(krem - ab);
          } }
    }
    __syncthreads();

    // ---- restore histograms to zero for the next replay ----
    #pragma unroll 4
    for (int j = t; j < 65536; j += 1024) g_hist[pass][b][j] = 0u;
    g_coarse[pass][b][t] = 0u;
    if (t == 0) g_done[pass][b] = 0u;
}

// ---------------------------------------------------------------------------
// Fused collect + bitonic sort + state reset. grid=(64,Bn), 1024 threads.
// ---------------------------------------------------------------------------
__global__ void __launch_bounds__(1024)
topk_collect_sort(const float* __restrict__ edge) {
    const int b = blockIdx.y;
    const int t = threadIdx.x;
    const int i = blockIdx.x * 1024 + t;
    const ull key = make_key(edge[(size_t)b * HWn + i], i);
    if (key >= g_prefix[b]) {
        const int p = atomicAdd(&g_candcnt[b], 1);
        if (p < Pn) g_cand[b][p] = key;   // exactly 256 (guard = OOB insurance)
    }

    __threadfence();
    __shared__ bool is_last;
    if (t == 0) {
        const unsigned int prev = atomicAdd(&g_done_c[b], 1u);
        is_last = (prev == 63u);
    }
    __syncthreads();
    if (!is_last) return;

    __shared__ ull keys[Pn];
    if (t < Pn) keys[t] = g_cand[b][t];
    __syncthreads();

    for (int kk = 2; kk <= Pn; kk <<= 1) {
        for (int jj = kk >> 1; jj > 0; jj >>= 1) {
            if (t < Pn) {
                const int ixj = t ^ jj;
                if (ixj > t) {
                    const ull a = keys[t];
                    const ull c = keys[ixj];
                    const bool up = ((t & kk) == 0);
                    if (up ? (a < c) : (a > c)) { keys[t] = c; keys[ixj] = a; }
                }
            }
            __syncthreads();
        }
    }
    if (t < Pn)
        g_idx[b * Pn + t] = (int)(0xFFFFu - (unsigned int)(keys[t] & 0xFFFFull));

    if (t == 0) {
        g_candcnt[b] = 0;
        g_done_c[b] = 0u;
        g_prefix[b] = 0ull;
        g_K[b] = Pn;
    }
}

// ---------------------------------------------------------------------------
// Gather: feat[b][n][d] = x[b][d][idx[b][n]]   grid (Pn, Bn), 256 threads (d)
// ---------------------------------------------------------------------------
__global__ void gather_kernel(const float* __restrict__ x) {
    const int b = blockIdx.y;
    const int n = blockIdx.x;
    const int d = threadIdx.x;
    const int col = g_idx[b * Pn + n];
    g_feat[((b * Pn + n) << 8) + d] =
        x[(size_t)b * Cn * HWn + (size_t)d * HWn + (size_t)col];
}

// ---------------------------------------------------------------------------
// GEMM1 (NN), double-buffered: Z = relu(BN(W_adj @ F)) + F
// 64x64 tile, KB=32, 2-stage smem ping-pong, float4 (16B-aligned) loads.
// ---------------------------------------------------------------------------
__global__ void __launch_bounds__(256)
gemm1_kernel(const float* __restrict__ W,
             const float* __restrict__ ga, const float* __restrict__ ba,
             const float* __restrict__ ma, const float* __restrict__ va) {
    __shared__ __align__(16) float sA[2][32][68];   // [stage][k][i]
    __shared__ __align__(16) float sB[2][32][68];   // [stage][k][d]

    const int b  = blockIdx.z;
    const float* F = g_feat + b * Pn * Cn;
    float* Z       = g_z    + b * Pn * Cn;
    const int ti = blockIdx.y * 64;
    const int td = blockIdx.x * 64;
    const int t  = threadIdx.x;
    const int tx = t & 15;
    const int ty = t >> 4;

    // A loads: 512 float4 per tile; thread handles f4 indices t and t+256.
    const int aI0 = t,       aI1 = t + 256;
    const int ai0 = aI0 >> 3, ak0 = (aI0 & 7) * 4;
    const int ai1 = aI1 >> 3, ak1 = (aI1 & 7) * 4;
    // B loads: f4 index -> bk = idx>>4, bd = (idx&15)*4
    const int bk0 = aI0 >> 4, bd0 = (aI0 & 15) * 4;
    const int bk1 = aI1 >> 4, bd1 = (aI1 & 15) * 4;

    float4 a0, a1, b0v, b1v;
    #define G1_LOAD(k0)                                                     \
        a0  = *(const float4*)&W[(ti + ai0) * Pn + (k0) + ak0];             \
        a1  = *(const float4*)&W[(ti + ai1) * Pn + (k0) + ak1];             \
        b0v = *(const float4*)&F[((k0) + bk0) * Cn + td + bd0];             \
        b1v = *(const float4*)&F[((k0) + bk1) * Cn + td + bd1];
    #define G1_STORE(st)                                                    \
        sA[st][ak0+0][ai0] = a0.x; sA[st][ak0+1][ai0] = a0.y;               \
        sA[st][ak0+2][ai0] = a0.z; sA[st][ak0+3][ai0] = a0.w;               \
        sA[st][ak1+0][ai1] = a1.x; sA[st][ak1+1][ai1] = a1.y;               \
        sA[st][ak1+2][ai1] = a1.z; sA[st][ak1+3][ai1] = a1.w;               \
        *(float4*)&sB[st][bk0][bd0] = b0v;                                  \
        *(float4*)&sB[st][bk1][bd1] = b1v;

    float acc[4][4] = {};

    G1_LOAD(0)
    G1_STORE(0)
    __syncthreads();

    #pragma unroll
    for (int kt = 0; kt < 8; ++kt) {
        const int st = kt & 1;
        if (kt < 7) { G1_LOAD((kt + 1) * 32) }
        #pragma unroll
        for (int k = 0; k < 32; ++k) {
            const float4 a4 = *(const float4*)&sA[st][k][ty * 4];
            const float4 b4 = *(const float4*)&sB[st][k][tx * 4];
            const float ar[4] = {a4.x, a4.y, a4.z, a4.w};
            const float br[4] = {b4.x, b4.y, b4.z, b4.w};
            #pragma unroll
            for (int ii = 0; ii < 4; ++ii)
                #pragma unroll
                for (int jj = 0; jj < 4; ++jj)
                    acc[ii][jj] += ar[ii] * br[jj];
        }
        if (kt < 7) { G1_STORE(st ^ 1) }
        __syncthreads();
    }

    #pragma unroll
    for (int ui = 0; ui < 4; ++ui) {
        const int i = ti + ty * 4 + ui;
        const float inv = ga[i] * rsqrtf(va[i] + EPSn);
        const float add = ba[i] - ma[i] * inv;
        #pragma unroll
        for (int ud = 0; ud < 4; ++ud) {
            const int d = td + tx * 4 + ud;
            Z[i * Cn + d] = fmaxf(acc[ui][ud] * inv + add, 0.0f) + F[i * Cn + d];
        }
    }
    #undef G1_LOAD
    #undef G1_STORE
}

// ---------------------------------------------------------------------------
// GEMM2 (NT), double-buffered: z2[p][c] = relu(BN(sum_d Z[p][d]*Wg[c][d]))
// ---------------------------------------------------------------------------
__global__ void __launch_bounds__(256)
gemm2_kernel(const float* __restrict__ Wg,
             const float* __restrict__ gw, const float* __restrict__ bw,
             const float* __restrict__ mw, const float* __restrict__ vw) {
    __shared__ __align__(16) float sA[2][32][68];   // [stage][k][p]
    __shared__ __align__(16) float sB[2][32][68];   // [stage][k][c]

    const int b = blockIdx.z;
    const float* Z = g_z  + b * Pn * Cn;
    float* Z2      = g_z2 + b * Pn * Cn;
    const int tp = blockIdx.y * 64;
    const int tc = blockIdx.x * 64;
    const int t  = threadIdx.x;
    const int tx = t & 15;
    const int ty = t >> 4;

    const int aI0 = t,       aI1 = t + 256;
    const int ar0 = aI0 >> 3, ak0 = (aI0 & 7) * 4;
    const int ar1 = aI1 >> 3, ak1 = (aI1 & 7) * 4;

    float4 a0, a1, b0v, b1v;
    #define G2_LOAD(k0)                                                     \
        a0  = *(const float4*)&Z[(tp + ar0) * Cn + (k0) + ak0];             \
        a1  = *(const float4*)&Z[(tp + ar1) * Cn + (k0) + ak1];             \
        b0v = *(const float4*)&Wg[(tc + ar0) * Cn + (k0) + ak0];            \
        b1v = *(const float4*)&Wg[(tc + ar1) * Cn + (k0) + ak1];
    #define G2_STORE(st)                                                    \
        sA[st][ak0+0][ar0] = a0.x; sA[st][ak0+1][ar0] = a0.y;               \
        sA[st][ak0+2][ar0] = a0.z; sA[st][ak0+3][ar0] = a0.w;               \
        sA[st][ak1+0][ar1] = a1.x; sA[st][ak1+1][ar1] = a1.y;               \
        sA[st][ak1+2][ar1] = a1.z; sA[st][ak1+3][ar1] = a1.w;               \
        sB[st][ak0+0][ar0] = b0v.x; sB[st][ak0+1][ar0] = b0v.y;             \
        sB[st][ak0+2][ar0] = b0v.z; sB[st][ak0+3][ar0] = b0v.w;             \
        sB[st][ak1+0][ar1] = b1v.x; sB[st][ak1+1][ar1] = b1v.y;             \
        sB[st][ak1+2][ar1] = b1v.z; sB[st][ak1+3][ar1] = b1v.w;

    float acc[4][4] = {};

    G2_LOAD(0)
    G2_STORE(0)
    __syncthreads();

    #pragma unroll
    for (int kt = 0; kt < 8; ++kt) {
        const int st = kt & 1;
        if (kt < 7) { G2_LOAD((kt + 1) * 32) }
        #pragma unroll
        for (int k = 0; k < 32; ++k) {
            const float4 a4 = *(const float4*)&sA[st][k][ty * 4];
            const float4 b4 = *(const float4*)&sB[st][k][tx * 4];
            const float ar[4] = {a4.x, a4.y, a4.z, a4.w};
            const float br[4] = {b4.x, b4.y, b4.z, b4.w};
            #pragma unroll
            for (int ii = 0; ii < 4; ++ii)
                #pragma unroll
                for (int jj = 0; jj < 4; ++jj)
                    acc[ii][jj] += ar[ii] * br[jj];
        }
        if (kt < 7) { G2_STORE(st ^ 1) }
        __syncthreads();
    }

    #pragma unroll
    for (int uc = 0; uc < 4; ++uc) {
        const int c = tc + tx * 4 + uc;
        const float inv = gw[c] * rsqrtf(vw[c] + EPSn);
        const float add = bw[c] - mw[c] * inv;
        #pragma unroll
        for (int ui = 0; ui < 4; ++ui) {
            const int p = tp + ty * 4 + ui;
            Z2[p * Cn + c] = fmaxf(acc[ui][uc] * inv + add, 0.0f);
        }
    }
    #undef G2_LOAD
    #undef G2_STORE
}

// ---------------------------------------------------------------------------
// Scatter: out[b, c, idx[b,p]] = z2[b,p,c].  grid (Pn, Bn), 256 threads (c).
// ---------------------------------------------------------------------------
__global__ void __launch_bounds__(256)
scatter_kernel(float* __restrict__ out) {
    const int b = blockIdx.y;
    const int p = blockIdx.x;
    const int c = threadIdx.x;
    const int col = g_idx[b * Pn + p];
    out[(size_t)b * Cn * HWn + (size_t)c * HWn + (size_t)col] =
        g_z2[((b * Pn + p) << 8) + c];
}

// ---------------------------------------------------------------------------
extern "C" void kernel_launch(void* const* d_in, const int* in_sizes, int n_in,
                              void* d_out, int out_size) {
    const float* x     = (const float*)d_in[0];
    const float* edge  = (const float*)d_in[1];
    const float* w_adj = (const float*)d_in[2];
    const float* g_adj = (const float*)d_in[3];
    const float* b_adj = (const float*)d_in[4];
    const float* m_adj = (const float*)d_in[5];
    const float* v_adj = (const float*)d_in[6];
    const float* w_wg  = (const float*)d_in[7];
    const float* g_wg  = (const float*)d_in[8];
    const float* b_wg  = (const float*)d_in[9];
    const float* m_wg  = (const float*)d_in[10];
    const float* v_wg  = (const float*)d_in[11];
    float* out = (float*)d_out;

    static cudaStream_t s1 = nullptr;
    static cudaEvent_t evA = nullptr, evB = nullptr;
    if (s1 == nullptr) {
        cudaStreamCreateWithFlags(&s1, cudaStreamNonBlocking);
        cudaEventCreateWithFlags(&evA, cudaEventDisableTiming);
        cudaEventCreateWithFlags(&evB, cudaEventDisableTiming);
    }

    // Fork side stream from stream 0.
    cudaEventRecord(evA, 0);
    cudaStreamWaitEvent(s1, evA, 0);

    // Stream 0: bulk copy x -> out on the SMs.
    copy_kernel<<<2048, 256>>>((const float4*)x, (float4*)out);

    // Side stream: exact top-256 (3 fused hist+scan passes, fused collect+sort).
    topk_pass<<<dim3(64, Bn), 1024, 0, s1>>>(edge, 2);
    topk_pass<<<dim3(64, Bn), 1024, 0, s1>>>(edge, 1);
    topk_pass<<<dim3(64, Bn), 1024, 0, s1>>>(edge, 0);
    topk_collect_sort<<<dim3(64, Bn), 1024, 0, s1>>>(edge);

    // Side stream: gather + GCN stage 1 + GCN stage 2 compute.
    gather_kernel<<<dim3(Pn, Bn), Cn, 0, s1>>>(x);
    gemm1_kernel<<<dim3(4, 4, Bn), 256, 0, s1>>>(w_adj, g_adj, b_adj, m_adj, v_adj);
    gemm2_kernel<<<dim3(4, 4, Bn), 256, 0, s1>>>(w_wg, g_wg, b_wg, m_wg, v_wg);

    // Join and scatter the reasoned point features into out.
    cudaEventRecord(evB, s1);
    cudaStreamWaitEvent(0, evB, 0);
    scatter_kernel<<<dim3(Pn, Bn), 256>>>(out);
}

// round 8
// speedup vs baseline: 1.0940x; 1.0940x over previous
#include <cuda_runtime.h>
#include <math.h>

// Problem dims (fixed by the dataset)
#define Bn   4
#define Cn   256
#define HWn  65536
#define Pn   256
#define THRESH_F 0.8f
#define EPSn 1e-5f

typedef unsigned long long ull;

// ---------------------------------------------------------------------------
// Scratch (no cudaMalloc allowed). All mutable state is restored by the
// kernels themselves (or the next kernel in the stream) so graph replays see
// identical initial state.
// ---------------------------------------------------------------------------
__device__ __align__(16) int   g_idx[Bn * Pn];
__device__ __align__(16) float g_feat[Bn * Pn * Cn];   // (B, P, C)
__device__ __align__(16) float g_z[Bn * Pn * Cn];      // (B, P, C)
__device__ __align__(16) float g_z2[Bn * Pn * Cn];     // (B, P, C)

__device__ unsigned int g_hist[3][Bn][65536];    // zero at rest
__device__ unsigned int g_coarse[3][Bn][1024];   // zero at rest
__device__ ull g_prefix[Bn];                     // zero at rest
__device__ int g_K[Bn] = {Pn, Pn, Pn, Pn};       // Pn at rest
__device__ int g_candcnt[Bn];                    // zero at rest
__device__ ull g_cand[Bn][Pn];
__device__ volatile unsigned int g_bar[Bn][8];   // zero at rest (reset by gather)

// ---------------------------------------------------------------------------
// 48-bit composite key: (monotone_float32 << 16) | (0xFFFF - idx)
// ---------------------------------------------------------------------------
__device__ __forceinline__ ull make_key(float e, int i) {
    float v = (e < THRESH_F) ? 0.0f : e;
    unsigned int ub = __float_as_uint(v);
    ub = (ub & 0x80000000u) ? ~ub : (ub | 0x80000000u);
    return ((ull)ub << 16) | (ull)(0xFFFFu - (unsigned int)i);
}

// ---------------------------------------------------------------------------
// SM bulk copy: out <- x  (256 MB). float4 grid-stride.
// ---------------------------------------------------------------------------
__global__ void __launch_bounds__(256)
copy_kernel(const float4* __restrict__ src, float4* __restrict__ dst) {
    const int n4 = Bn * Cn * HWn / 4;
    int i = blockIdx.x * blockDim.x + threadIdx.x;
    const int stride = gridDim.x * blockDim.x;
    for (; i < n4; i += stride) dst[i] = src[i];
}

// ---------------------------------------------------------------------------
// Per-batch global barrier over NB blocks (counter + volatile spin).
// Publishing pattern: every thread fences, block syncs, thread 0 arrives.
// ---------------------------------------------------------------------------
#define NBLK 16
__device__ __forceinline__ void batch_barrier(int b, int slot) {
    __threadfence();
    __syncthreads();
    if (threadIdx.x == 0) {
        atomicAdd((unsigned int*)&g_bar[b][slot], 1u);
        while (g_bar[b][slot] < NBLK) { }
        __threadfence();
    }
    __syncthreads();
}

// ---------------------------------------------------------------------------
// Whole top-256 in ONE launch. grid = (NBLK, Bn), 1024 threads.
// Each thread owns 4 consecutive elements (keys live in registers across all
// passes). 3 radix passes (16-bit digits) + collect + bitonic sort.
// ---------------------------------------------------------------------------
__global__ void __launch_bounds__(1024)
topk_all(const float* __restrict__ edge) {
    const int b   = blockIdx.y;
    const int blk = blockIdx.x;
    const int t   = threadIdx.x;
    const int lane = t & 31;
    const int w    = t >> 5;

    const int ibase = blk * 4096 + t * 4;
    const float4 ev = *(const float4*)&edge[(size_t)b * HWn + ibase];
    ull key[4];
    key[0] = make_key(ev.x, ibase + 0);
    key[1] = make_key(ev.y, ibase + 1);
    key[2] = make_key(ev.z, ibase + 2);
    key[3] = make_key(ev.w, ibase + 3);

    __shared__ unsigned int warpsum[32];
    __shared__ unsigned int warpsuf[32];
    __shared__ int sh_chunk;
    __shared__ unsigned int sh_krem;
    __shared__ unsigned int bins[64];
    __shared__ ull skeys[Pn];

    #pragma unroll
    for (int pass = 2; pass >= 0; --pass) {
        // ---- histogram (fine + coarse), warp-aggregated atomics ----
        const ull pre = (pass == 2) ? 0ull : *(volatile ull*)&g_prefix[b];
        #pragma unroll
        for (int j = 0; j < 4; ++j) {
            const bool active = (pass == 2) ||
                                ((key[j] >> ((pass + 1) * 16)) == pre);
            const unsigned int bin =
                (unsigned int)((key[j] >> (pass * 16)) & 0xFFFFull);
            const unsigned int amask = __ballot_sync(0xFFFFFFFFu, active);
            if (active) {
                unsigned int peers = __match_any_sync(amask, bin);
                if (lane == __ffs(peers) - 1)
                    atomicAdd(&g_hist[pass][b][bin], (unsigned int)__popc(peers));
                unsigned int peersc = __match_any_sync(amask, bin >> 6);
                if (lane == __ffs(peersc) - 1)
                    atomicAdd(&g_coarse[pass][b][bin >> 6], (unsigned int)__popc(peersc));
            }
        }

        batch_barrier(b, pass * 2);

        // ---- scan by block 0 of each batch ----
        if (blk == 0) {
            const unsigned int mine = g_coarse[pass][b][t];
            unsigned int suf = mine;
            #pragma unroll
            for (int off = 1; off < 32; off <<= 1) {
                const unsigned int v = __shfl_down_sync(0xFFFFFFFFu, suf, off);
                if (lane + off < 32) suf += v;
            }
            if (lane == 0) warpsum[w] = suf;
            __syncthreads();

            if (w == 0) {
                const unsigned int ws = warpsum[lane];
                unsigned int wsuf = ws;
                #pragma unroll
                for (int off = 1; off < 32; off <<= 1) {
                    const unsigned int v = __shfl_down_sync(0xFFFFFFFFu, wsuf, off);
                    if (lane + off < 32) wsuf += v;
                }
                warpsuf[lane] = wsuf - ws;
            }
            __syncthreads();

            const unsigned int K = (unsigned int)g_K[b];
            const unsigned int suf_t = suf + warpsuf[w];
            const unsigned int above = suf_t - mine;
            if (suf_t >= K && above < K) {
                sh_chunk = t;
                sh_krem = K - above;
            }
            __syncthreads();

            const int chunk = sh_chunk;
            if (t < 64) bins[t] = g_hist[pass][b][chunk * 64 + t];
            __syncthreads();

            if (w == 0) {
                const unsigned int krem = sh_krem;
                const unsigned int lo = bins[lane];
                const unsigned int hi = bins[lane + 32];

                unsigned int suf_hi = hi;
                #pragma unroll
                for (int off = 1; off < 32; off <<= 1) {
                    const unsigned int v = __shfl_down_sync(0xFFFFFFFFu, suf_hi, off);
                    if (lane + off < 32) suf_hi += v;
                }
                const unsigned int hi_total = __shfl_sync(0xFFFFFFFFu, suf_hi, 0);

                unsigned int suf_lo = lo;
                #pragma unroll
                for (int off = 1; off < 32; off <<= 1) {
                    const unsigned int v = __shfl_down_sync(0xFFFFFFFFu, suf_lo, off);
                    if (lane + off < 32) suf_lo += v;
                }
                suf_lo += hi_total;

                { const unsigned int st = suf_hi, ab = st - hi;
                  if (st >= krem && ab < krem) {
                      g_prefix[b] = (g_prefix[b] << 16) | (ull)(chunk * 64 + 32 + lane);
                      g_K[b] = (int)(krem - ab);
                  } }
                { const unsigned int st = suf_lo, ab = st - lo;
                  if (st >= krem && ab < krem) {
                      g_prefix[b] = (g_prefix[b] << 16) | (ull)(chunk * 64 + lane);
                      g_K[b] = (int)(krem - ab);
                  } }
            }
            __syncthreads();
        }

        batch_barrier(b, pass * 2 + 1);
    }

    // ---- collect the exact 256 winners ----
    const ull cutoff = *(volatile ull*)&g_prefix[b];
    #pragma unroll
    for (int j = 0; j < 4; ++j) {
        if (key[j] >= cutoff) {
            const int p = atomicAdd(&g_candcnt[b], 1);
            if (p < Pn) g_cand[b][p] = key[j];   // exactly 256 (keys unique)
        }
    }

    batch_barrier(b, 6);

    // ---- sort + emit indices (block 0) ----
    if (blk == 0) {
        if (t < Pn) skeys[t] = g_cand[b][t];
        __syncthreads();
        for (int kk = 2; kk <= Pn; kk <<= 1) {
            for (int jj = kk >> 1; jj > 0; jj >>= 1) {
                if (t < Pn) {
                    const int ixj = t ^ jj;
                    if (ixj > t) {
                        const ull a = skeys[t];
                        const ull c = skeys[ixj];
                        const bool up = ((t & kk) == 0);
                        if (up ? (a < c) : (a > c)) { skeys[t] = c; skeys[ixj] = a; }
                    }
                }
                __syncthreads();
            }
        }
        if (t < Pn)
            g_idx[b * Pn + t] = (int)(0xFFFFu - (unsigned int)(skeys[t] & 0xFFFFull));
        if (t == 0) {
            g_candcnt[b] = 0;
            g_prefix[b] = 0ull;
            g_K[b] = Pn;
        }
    }

    // ---- restore histograms to zero for the next replay (all blocks) ----
    const int gt = blk * 1024 + t;                 // 0..16383 per batch
    #pragma unroll
    for (int p = 0; p < 3; ++p) {
        #pragma unroll
        for (int r = 0; r < 4; ++r)
            g_hist[p][b][gt + r * 16384] = 0u;
        if (gt < 1024) g_coarse[p][b][gt] = 0u;
    }
    // NOTE: g_bar reset happens in gather_kernel (strictly after this kernel).
}

// ---------------------------------------------------------------------------
// Gather: feat[b][n][d] = x[b][d][idx[b][n]]   grid (Pn, Bn), 256 threads (d)
// Also resets topk barrier counters for the next graph replay.
// ---------------------------------------------------------------------------
__global__ void gather_kernel(const float* __restrict__ x) {
    const int b = blockIdx.y;
    const int n = blockIdx.x;
    const int d = threadIdx.x;
    if (n == 0 && d < 8) g_bar[b][d] = 0u;
    const int col = g_idx[b * Pn + n];
    g_feat[((b * Pn + n) << 8) + d] =
        x[(size_t)b * Cn * HWn + (size_t)d * HWn + (size_t)col];
}

// ---------------------------------------------------------------------------
// GEMM1 (NN): Z[b,i,d] = relu(BN_adj(sum_j W_adj[i,j]*feat[b,j,d])) + feat[b,i,d]
// (round-5 proven version)
// ---------------------------------------------------------------------------
__global__ void __launch_bounds__(256)
gemm1_kernel(const float* __restrict__ W,
             const float* __restrict__ ga, const float* __restrict__ ba,
             const float* __restrict__ ma, const float* __restrict__ va) {
    __shared__ __align__(16) float sA[16][64 + 4];
    __shared__ __align__(16) float sB[16][64 + 4];

    const int b  = blockIdx.z;
    const float* F = g_feat + b * Pn * Cn;
    float* Z       = g_z    + b * Pn * Cn;
    const int ti = blockIdx.y * 64;
    const int td = blockIdx.x * 64;
    const int tx = threadIdx.x & 15;
    const int ty = threadIdx.x >> 4;

    float acc[4][4] = {};

    for (int k0 = 0; k0 < Pn; k0 += 16) {
        #pragma unroll
        for (int r = 0; r < 4; ++r) {
            const int eI = threadIdx.x + r * 256;
            const int ai = eI >> 4, ak = eI & 15;
            sA[ak][ai] = W[(ti + ai) * Pn + (k0 + ak)];
            const int bk = eI >> 6, bd = eI & 63;
            sB[bk][bd] = F[(k0 + bk) * Cn + (td + bd)];
        }
        __syncthreads();
        #pragma unroll
        for (int k = 0; k < 16; ++k) {
            const float4 a4 = *(const float4*)&sA[k][ty * 4];
            const float4 b4 = *(const float4*)&sB[k][tx * 4];
            const float a0[4] = {a4.x, a4.y, a4.z, a4.w};
            const float b0[4] = {b4.x, b4.y, b4.z, b4.w};
            #pragma unroll
            for (int i = 0; i < 4; ++i)
                #pragma unroll
                for (int j = 0; j < 4; ++j)
                    acc[i][j] += a0[i] * b0[j];
        }
        __syncthreads();
    }

    #pragma unroll
    for (int ui = 0; ui < 4; ++ui) {
        const int i = ti + ty * 4 + ui;
        const float inv = ga[i] * rsqrtf(va[i] + EPSn);
        const float add = ba[i] - ma[i] * inv;
        #pragma unroll
        for (int ud = 0; ud < 4; ++ud) {
            const int d = td + tx * 4 + ud;
            Z[i * Cn + d] = fmaxf(acc[ui][ud] * inv + add, 0.0f) + F[i * Cn + d];
        }
    }
}

// ---------------------------------------------------------------------------
// GEMM2 (NT): z2[b,p,c] = relu(BN_wg(sum_d Z[b,p,d]*Wg[c,d]))
// (round-5 proven version)
// ---------------------------------------------------------------------------
__global__ void __launch_bounds__(256)
gemm2_kernel(const float* __restrict__ Wg,
             const float* __restrict__ gw, const float* __restrict__ bw,
             const float* __restrict__ mw, const float* __restrict__ vw) {
    __shared__ __align__(16) float sA[16][64 + 4];
    __shared__ __align__(16) float sB[16][64 + 4];

    const int b = blockIdx.z;
    const float* Z = g_z  + b * Pn * Cn;
    float* Z2      = g_z2 + b * Pn * Cn;
    const int tp = blockIdx.y * 64;
    const int tc = blockIdx.x * 64;
    const int tx = threadIdx.x & 15;
    const int ty = threadIdx.x >> 4;

    float acc[4][4] = {};

    for (int k0 = 0; k0 < Cn; k0 += 16) {
        #pragma unroll
        for (int r = 0; r < 4; ++r) {
            const int eI = threadIdx.x + r * 256;
            const int ar = eI >> 4, ak = eI & 15;
            sA[ak][ar] = Z[(tp + ar) * Cn + (k0 + ak)];
            sB[ak][ar] = Wg[(tc + ar) * Cn + (k0 + ak)];
        }
        __syncthreads();
        #pragma unroll
        for (int k = 0; k < 16; ++k) {
            const float4 a4 = *(const float4*)&sA[k][ty * 4];
            const float4 b4 = *(const float4*)&sB[k][tx * 4];
            const float a0[4] = {a4.x, a4.y, a4.z, a4.w};
            const float b0[4] = {b4.x, b4.y, b4.z, b4.w};
            #pragma unroll
            for (int i = 0; i < 4; ++i)
                #pragma unroll
                for (int j = 0; j < 4; ++j)
                    acc[i][j] += a0[i] * b0[j];
        }
        __syncthreads();
    }

    #pragma unroll
    for (int uc = 0; uc < 4; ++uc) {
        const int c = tc + tx * 4 + uc;
        const float inv = gw[c] * rsqrtf(vw[c] + EPSn);
        const float add = bw[c] - mw[c] * inv;
        #pragma unroll
        for (int ui = 0; ui < 4; ++ui) {
            const int p = tp + ty * 4 + ui;
            Z2[p * Cn + c] = fmaxf(acc[ui][uc] * inv + add, 0.0f);
        }
    }
}

// ---------------------------------------------------------------------------
// Scatter: out[b, c, idx[b,p]] = z2[b,p,c].  grid (Pn, Bn), 256 threads (c).
// ---------------------------------------------------------------------------
__global__ void __launch_bounds__(256)
scatter_kernel(float* __restrict__ out) {
    const int b = blockIdx.y;
    const int p = blockIdx.x;
    const int c = threadIdx.x;
    const int col = g_idx[b * Pn + p];
    out[(size_t)b * Cn * HWn + (size_t)c * HWn + (size_t)col] =
        g_z2[((b * Pn + p) << 8) + c];
}

// ---------------------------------------------------------------------------
extern "C" void kernel_launch(void* const* d_in, const int* in_sizes, int n_in,
                              void* d_out, int out_size) {
    const float* x     = (const float*)d_in[0];
    const float* edge  = (const float*)d_in[1];
    const float* w_adj = (const float*)d_in[2];
    const float* g_adj = (const float*)d_in[3];
    const float* b_adj = (const float*)d_in[4];
    const float* m_adj = (const float*)d_in[5];
    const float* v_adj = (const float*)d_in[6];
    const float* w_wg  = (const float*)d_in[7];
    const float* g_wg  = (const float*)d_in[8];
    const float* b_wg  = (const float*)d_in[9];
    const float* m_wg  = (const float*)d_in[10];
    const float* v_wg  = (const float*)d_in[11];
    float* out = (float*)d_out;

    static cudaStream_t s1 = nullptr;
    static cudaEvent_t evA = nullptr, evB = nullptr;
    if (s1 == nullptr) {
        cudaStreamCreateWithFlags(&s1, cudaStreamNonBlocking);
        cudaEventCreateWithFlags(&evA, cudaEventDisableTiming);
        cudaEventCreateWithFlags(&evB, cudaEventDisableTiming);
    }

    // Fork side stream from stream 0.
    cudaEventRecord(evA, 0);
    cudaStreamWaitEvent(s1, evA, 0);

    // Stream 0: bulk copy x -> out on the SMs.
    copy_kernel<<<2048, 256>>>((const float4*)x, (float4*)out);

    // Side stream: whole exact top-256 in one launch, then point pipeline.
    topk_all<<<dim3(NBLK, Bn), 1024, 0, s1>>>(edge);
    gather_kernel<<<dim3(Pn, Bn), Cn, 0, s1>>>(x);
    gemm1_kernel<<<dim3(4, 4, Bn), 256, 0, s1>>>(w_adj, g_adj, b_adj, m_adj, v_adj);
    gemm2_kernel<<<dim3(4, 4, Bn), 256, 0, s1>>>(w_wg, g_wg, b_wg, m_wg, v_wg);

    // Join and scatter the reasoned point features into out.
    cudaEventRecord(evB, s1);
    cudaStreamWaitEvent(0, evB, 0);
    scatter_kernel<<<dim3(Pn, Bn), 256>>>(out);
}

// round 9
// speedup vs baseline: 1.2663x; 1.1575x over previous
#include <cuda_runtime.h>
#include <math.h>

// Problem dims (fixed by the dataset)
#define Bn   4
#define Cn   256
#define HWn  65536
#define Pn   256
#define THRESH_F 0.8f
#define EPSn 1e-5f

typedef unsigned long long ull;

// ---------------------------------------------------------------------------
// Scratch (no cudaMalloc allowed). All mutable state is restored by the
// kernels themselves (or the next kernel in the stream) so graph replays see
// identical initial state.
// ---------------------------------------------------------------------------
__device__ __align__(16) int   g_idx[Bn * Pn];
__device__ __align__(16) float g_feat[Bn * Pn * Cn];   // (B, P, C)
__device__ __align__(16) float g_z[Bn * Pn * Cn];      // (B, P, C)
__device__ __align__(16) float g_z2[Bn * Pn * Cn];     // (B, P, C)

__device__ unsigned int g_hist[3][Bn][65536];    // zero at rest
__device__ unsigned int g_coarse[3][Bn][1024];   // zero at rest
__device__ ull g_prefix[Bn];                     // zero at rest
__device__ int g_K[Bn] = {Pn, Pn, Pn, Pn};       // Pn at rest
__device__ int g_candcnt[Bn];                    // zero at rest
__device__ ull g_cand[Bn][Pn];
__device__ volatile unsigned int g_bar[Bn][8];   // zero at rest (reset by gather)

// ---------------------------------------------------------------------------
// 48-bit composite key: (monotone_float32 << 16) | (0xFFFF - idx)
// ---------------------------------------------------------------------------
__device__ __forceinline__ ull make_key(float e, int i) {
    float v = (e < THRESH_F) ? 0.0f : e;
    unsigned int ub = __float_as_uint(v);
    ub = (ub & 0x80000000u) ? ~ub : (ub | 0x80000000u);
    return ((ull)ub << 16) | (ull)(0xFFFFu - (unsigned int)i);
}

// ---------------------------------------------------------------------------
// SM bulk copy: out <- x  (256 MB). float4 grid-stride.
// 512 CTAs: enough MLP to hit the LTS cap, but leaves SM residency for the
// concurrent side-stream kernels.
// ---------------------------------------------------------------------------
__global__ void __launch_bounds__(256)
copy_kernel(const float4* __restrict__ src, float4* __restrict__ dst) {
    const int n4 = Bn * Cn * HWn / 4;
    int i = blockIdx.x * blockDim.x + threadIdx.x;
    const int stride = gridDim.x * blockDim.x;
    for (; i < n4; i += stride) dst[i] = src[i];
}

// ---------------------------------------------------------------------------
// Per-batch global barrier over NBLK blocks (counter + volatile spin).
// ---------------------------------------------------------------------------
#define NBLK 16
__device__ __forceinline__ void batch_barrier(int b, int slot) {
    __threadfence();
    __syncthreads();
    if (threadIdx.x == 0) {
        atomicAdd((unsigned int*)&g_bar[b][slot], 1u);
        while (g_bar[b][slot] < NBLK) { }
        __threadfence();
    }
    __syncthreads();
}

// ---------------------------------------------------------------------------
// Whole top-256 in ONE launch. grid = (NBLK, Bn), 1024 threads.
// Keys live in registers across all 3 radix passes + collect.
// ---------------------------------------------------------------------------
__global__ void __launch_bounds__(1024)
topk_all(const float* __restrict__ edge) {
    const int b   = blockIdx.y;
    const int blk = blockIdx.x;
    const int t   = threadIdx.x;
    const int lane = t & 31;
    const int w    = t >> 5;

    const int ibase = blk * 4096 + t * 4;
    const float4 ev = *(const float4*)&edge[(size_t)b * HWn + ibase];
    ull key[4];
    key[0] = make_key(ev.x, ibase + 0);
    key[1] = make_key(ev.y, ibase + 1);
    key[2] = make_key(ev.z, ibase + 2);
    key[3] = make_key(ev.w, ibase + 3);

    __shared__ unsigned int warpsum[32];
    __shared__ unsigned int warpsuf[32];
    __shared__ int sh_chunk;
    __shared__ unsigned int sh_krem;
    __shared__ unsigned int bins[64];
    __shared__ ull skeys[Pn];

    #pragma unroll
    for (int pass = 2; pass >= 0; --pass) {
        const ull pre = (pass == 2) ? 0ull : *(volatile ull*)&g_prefix[b];
        #pragma unroll
        for (int j = 0; j < 4; ++j) {
            const bool active = (pass == 2) ||
                                ((key[j] >> ((pass + 1) * 16)) == pre);
            const unsigned int bin =
                (unsigned int)((key[j] >> (pass * 16)) & 0xFFFFull);
            const unsigned int amask = __ballot_sync(0xFFFFFFFFu, active);
            if (active) {
                unsigned int peers = __match_any_sync(amask, bin);
                if (lane == __ffs(peers) - 1)
                    atomicAdd(&g_hist[pass][b][bin], (unsigned int)__popc(peers));
                unsigned int peersc = __match_any_sync(amask, bin >> 6);
                if (lane == __ffs(peersc) - 1)
                    atomicAdd(&g_coarse[pass][b][bin >> 6], (unsigned int)__popc(peersc));
            }
        }

        batch_barrier(b, pass * 2);

        if (blk == 0) {
            const unsigned int mine = g_coarse[pass][b][t];
            unsigned int suf = mine;
            #pragma unroll
            for (int off = 1; off < 32; off <<= 1) {
                const unsigned int v = __shfl_down_sync(0xFFFFFFFFu, suf, off);
                if (lane + off < 32) suf += v;
            }
            if (lane == 0) warpsum[w] = suf;
            __syncthreads();

            if (w == 0) {
                const unsigned int ws = warpsum[lane];
                unsigned int wsuf = ws;
                #pragma unroll
                for (int off = 1; off < 32; off <<= 1) {
                    const unsigned int v = __shfl_down_sync(0xFFFFFFFFu, wsuf, off);
                    if (lane + off < 32) wsuf += v;
                }
                warpsuf[lane] = wsuf - ws;
            }
            __syncthreads();

            const unsigned int K = (unsigned int)g_K[b];
            const unsigned int suf_t = suf + warpsuf[w];
            const unsigned int above = suf_t - mine;
            if (suf_t >= K && above < K) {
                sh_chunk = t;
                sh_krem = K - above;
            }
            __syncthreads();

            const int chunk = sh_chunk;
            if (t < 64) bins[t] = g_hist[pass][b][chunk * 64 + t];
            __syncthreads();

            if (w == 0) {
                const unsigned int krem = sh_krem;
                const unsigned int lo = bins[lane];
                const unsigned int hi = bins[lane + 32];

                unsigned int suf_hi = hi;
                #pragma unroll
                for (int off = 1; off < 32; off <<= 1) {
                    const unsigned int v = __shfl_down_sync(0xFFFFFFFFu, suf_hi, off);
                    if (lane + off < 32) suf_hi += v;
                }
                const unsigned int hi_total = __shfl_sync(0xFFFFFFFFu, suf_hi, 0);

                unsigned int suf_lo = lo;
                #pragma unroll
                for (int off = 1; off < 32; off <<= 1) {
                    const unsigned int v = __shfl_down_sync(0xFFFFFFFFu, suf_lo, off);
                    if (lane + off < 32) suf_lo += v;
                }
                suf_lo += hi_total;

                { const unsigned int st = suf_hi, ab = st - hi;
                  if (st >= krem && ab < krem) {
                      g_prefix[b] = (g_prefix[b] << 16) | (ull)(chunk * 64 + 32 + lane);
                      g_K[b] = (int)(krem - ab);
                  } }
                { const unsigned int st = suf_lo, ab = st - lo;
                  if (st >= krem && ab < krem) {
                      g_prefix[b] = (g_prefix[b] << 16) | (ull)(chunk * 64 + lane);
                      g_K[b] = (int)(krem - ab);
                  } }
            }
            __syncthreads();
        }

        batch_barrier(b, pass * 2 + 1);
    }

    const ull cutoff = *(volatile ull*)&g_prefix[b];
    #pragma unroll
    for (int j = 0; j < 4; ++j) {
        if (key[j] >= cutoff) {
            const int p = atomicAdd(&g_candcnt[b], 1);
            if (p < Pn) g_cand[b][p] = key[j];
        }
    }

    batch_barrier(b, 6);

    if (blk == 0) {
        if (t < Pn) skeys[t] = g_cand[b][t];
        __syncthreads();
        for (int kk = 2; kk <= Pn; kk <<= 1) {
            for (int jj = kk >> 1; jj > 0; jj >>= 1) {
                if (t < Pn) {
                    const int ixj = t ^ jj;
                    if (ixj > t) {
                        const ull a = skeys[t];
                        const ull c = skeys[ixj];
                        const bool up = ((t & kk) == 0);
                        if (up ? (a < c) : (a > c)) { skeys[t] = c; skeys[ixj] = a; }
                    }
                }
                __syncthreads();
            }
        }
        if (t < Pn)
            g_idx[b * Pn + t] = (int)(0xFFFFu - (unsigned int)(skeys[t] & 0xFFFFull));
        if (t == 0) {
            g_candcnt[b] = 0;
            g_prefix[b] = 0ull;
            g_K[b] = Pn;
        }
    }

    const int gt = blk * 1024 + t;
    #pragma unroll
    for (int p = 0; p < 3; ++p) {
        #pragma unroll
        for (int r = 0; r < 4; ++r)
            g_hist[p][b][gt + r * 16384] = 0u;
        if (gt < 1024) g_coarse[p][b][gt] = 0u;
    }
    // g_bar reset happens in gather_kernel (strictly after this kernel).
}

// ---------------------------------------------------------------------------
// Gather: feat[b][n][d] = x[b][d][idx[b][n]]   grid (Pn, Bn), 256 threads (d)
// Also resets topk barrier counters for the next graph replay.
// ---------------------------------------------------------------------------
__global__ void gather_kernel(const float* __restrict__ x) {
    const int b = blockIdx.y;
    const int n = blockIdx.x;
    const int d = threadIdx.x;
    if (n == 0 && d < 8) g_bar[b][d] = 0u;
    const int col = g_idx[b * Pn + n];
    g_feat[((b * Pn + n) << 8) + d] =
        x[(size_t)b * Cn * HWn + (size_t)d * HWn + (size_t)col];
}

// ---------------------------------------------------------------------------
// GEMM1 (NN): Z[b,i,d] = relu(BN_adj(sum_j W_adj[i,j]*feat[b,j,d])) + feat[b,i,d]
// ---------------------------------------------------------------------------
__global__ void __launch_bounds__(256)
gemm1_kernel(const float* __restrict__ W,
             const float* __restrict__ ga, const float* __restrict__ ba,
             const float* __restrict__ ma, const float* __restrict__ va) {
    __shared__ __align__(16) float sA[16][64 + 4];
    __shared__ __align__(16) float sB[16][64 + 4];

    const int b  = blockIdx.z;
    const float* F = g_feat + b * Pn * Cn;
    float* Z       = g_z    + b * Pn * Cn;
    const int ti = blockIdx.y * 64;
    const int td = blockIdx.x * 64;
    const int tx = threadIdx.x & 15;
    const int ty = threadIdx.x >> 4;

    float acc[4][4] = {};

    for (int k0 = 0; k0 < Pn; k0 += 16) {
        #pragma unroll
        for (int r = 0; r < 4; ++r) {
            const int eI = threadIdx.x + r * 256;
            const int ai = eI >> 4, ak = eI & 15;
            sA[ak][ai] = W[(ti + ai) * Pn + (k0 + ak)];
            const int bk = eI >> 6, bd = eI & 63;
            sB[bk][bd] = F[(k0 + bk) * Cn + (td + bd)];
        }
        __syncthreads();
        #pragma unroll
        for (int k = 0; k < 16; ++k) {
            const float4 a4 = *(const float4*)&sA[k][ty * 4];
            const float4 b4 = *(const float4*)&sB[k][tx * 4];
            const float a0[4] = {a4.x, a4.y, a4.z, a4.w};
            const float b0[4] = {b4.x, b4.y, b4.z, b4.w};
            #pragma unroll
            for (int i = 0; i < 4; ++i)
                #pragma unroll
                for (int j = 0; j < 4; ++j)
                    acc[i][j] += a0[i] * b0[j];
        }
        __syncthreads();
    }

    #pragma unroll
    for (int ui = 0; ui < 4; ++ui) {
        const int i = ti + ty * 4 + ui;
        const float inv = ga[i] * rsqrtf(va[i] + EPSn);
        const float add = ba[i] - ma[i] * inv;
        #pragma unroll
        for (int ud = 0; ud < 4; ++ud) {
            const int d = td + tx * 4 + ud;
            Z[i * Cn + d] = fmaxf(acc[ui][ud] * inv + add, 0.0f) + F[i * Cn + d];
        }
    }
}

// ---------------------------------------------------------------------------
// GEMM2 (NT): z2[b,p,c] = relu(BN_wg(sum_d Z[b,p,d]*Wg[c,d]))
// ---------------------------------------------------------------------------
__global__ void __launch_bounds__(256)
gemm2_kernel(const float* __restrict__ Wg,
             const float* __restrict__ gw, const float* __restrict__ bw,
             const float* __restrict__ mw, const float* __restrict__ vw) {
    __shared__ __align__(16) float sA[16][64 + 4];
    __shared__ __align__(16) float sB[16][64 + 4];

    const int b = blockIdx.z;
    const float* Z = g_z  + b * Pn * Cn;
    float* Z2      = g_z2 + b * Pn * Cn;
    const int tp = blockIdx.y * 64;
    const int tc = blockIdx.x * 64;
    const int tx = threadIdx.x & 15;
    const int ty = threadIdx.x >> 4;

    float acc[4][4] = {};

    for (int k0 = 0; k0 < Cn; k0 += 16) {
        #pragma unroll
        for (int r = 0; r < 4; ++r) {
            const int eI = threadIdx.x + r * 256;
            const int ar = eI >> 4, ak = eI & 15;
            sA[ak][ar] = Z[(tp + ar) * Cn + (k0 + ak)];
            sB[ak][ar] = Wg[(tc + ar) * Cn + (k0 + ak)];
        }
        __syncthreads();
        #pragma unroll
        for (int k = 0; k < 16; ++k) {
            const float4 a4 = *(const float4*)&sA[k][ty * 4];
            const float4 b4 = *(const float4*)&sB[k][tx * 4];
            const float a0[4] = {a4.x, a4.y, a4.z, a4.w};
            const float b0[4] = {b4.x, b4.y, b4.z, b4.w};
            #pragma unroll
            for (int i = 0; i < 4; ++i)
                #pragma unroll
                for (int j = 0; j < 4; ++j)
                    acc[i][j] += a0[i] * b0[j];
        }
        __syncthreads();
    }

    #pragma unroll
    for (int uc = 0; uc < 4; ++uc) {
        const int c = tc + tx * 4 + uc;
        const float inv = gw[c] * rsqrtf(vw[c] + EPSn);
        const float add = bw[c] - mw[c] * inv;
        #pragma unroll
        for (int ui = 0; ui < 4; ++ui) {
            const int p = tp + ty * 4 + ui;
            Z2[p * Cn + c] = fmaxf(acc[ui][uc] * inv + add, 0.0f);
        }
    }
}

// ---------------------------------------------------------------------------
// Scatter: out[b, c, idx[b,p]] = z2[b,p,c].  grid (Pn, Bn), 256 threads (c).
// ---------------------------------------------------------------------------
__global__ void __launch_bounds__(256)
scatter_kernel(float* __restrict__ out) {
    const int b = blockIdx.y;
    const int p = blockIdx.x;
    const int c = threadIdx.x;
    const int col = g_idx[b * Pn + p];
    out[(size_t)b * Cn * HWn + (size_t)c * HWn + (size_t)col] =
        g_z2[((b * Pn + p) << 8) + c];
}

// ---------------------------------------------------------------------------
extern "C" void kernel_launch(void* const* d_in, const int* in_sizes, int n_in,
                              void* d_out, int out_size) {
    const float* x     = (const float*)d_in[0];
    const float* edge  = (const float*)d_in[1];
    const float* w_adj = (const float*)d_in[2];
    const float* g_adj = (const float*)d_in[3];
    const float* b_adj = (const float*)d_in[4];
    const float* m_adj = (const float*)d_in[5];
    const float* v_adj = (const float*)d_in[6];
    const float* w_wg  = (const float*)d_in[7];
    const float* g_wg  = (const float*)d_in[8];
    const float* b_wg  = (const float*)d_in[9];
    const float* m_wg  = (const float*)d_in[10];
    const float* v_wg  = (const float*)d_in[11];
    float* out = (float*)d_out;

    static cudaStream_t s1 = nullptr;
    static cudaEvent_t evA = nullptr, evB = nullptr;
    if (s1 == nullptr) {
        int lo = 0, hi = 0;
        cudaDeviceGetStreamPriorityRange(&lo, &hi);   // hi = greatest priority
        cudaStreamCreateWithPriority(&s1, cudaStreamNonBlocking, hi);
        cudaEventCreateWithFlags(&evA, cudaEventDisableTiming);
        cudaEventCreateWithFlags(&evB, cudaEventDisableTiming);
    }

    // Fork side stream from stream 0.
    cudaEventRecord(evA, 0);
    cudaStreamWaitEvent(s1, evA, 0);

    // High-priority side stream first: topk -> gather -> GEMMs.
    topk_all<<<dim3(NBLK, Bn), 1024, 0, s1>>>(edge);
    gather_kernel<<<dim3(Pn, Bn), Cn, 0, s1>>>(x);
    gemm1_kernel<<<dim3(4, 4, Bn), 256, 0, s1>>>(w_adj, g_adj, b_adj, m_adj, v_adj);
    gemm2_kernel<<<dim3(4, 4, Bn), 256, 0, s1>>>(w_wg, g_wg, b_wg, m_wg, v_wg);

    // Stream 0: bulk copy x -> out on the SMs (512 CTAs: leaves residency).
    copy_kernel<<<512, 256>>>((const float4*)x, (float4*)out);

    // Join and scatter the reasoned point features into out.
    cudaEventRecord(evB, s1);
    cudaStreamWaitEvent(0, evB, 0);
    scatter_kernel<<<dim3(Pn, Bn), 256>>>(out);
}

// round 10
// speedup vs baseline: 1.3046x; 1.0302x over previous
#include <cuda_runtime.h>
#include <math.h>

// Problem dims (fixed by the dataset)
#define Bn   4
#define Cn   256
#define HWn  65536
#define Pn   256
#define THRESH_F 0.8f
#define EPSn 1e-5f

typedef unsigned long long ull;

// ---------------------------------------------------------------------------
// Scratch (no cudaMalloc allowed). All mutable state is restored by the
// kernels themselves (or the next kernel in the stream) so graph replays see
// identical initial state.
// ---------------------------------------------------------------------------
__device__ __align__(16) int   g_idx[Bn * Pn];
__device__ __align__(16) float g_feat[Bn * Pn * Cn];   // (B, P, C)
__device__ __align__(16) float g_z[Bn * Pn * Cn];      // (B, P, C)
__device__ __align__(16) float g_z2[Bn * Pn * Cn];     // (B, P, C)

__device__ unsigned int g_hist[3][Bn][65536];    // zero at rest
__device__ unsigned int g_coarse[3][Bn][1024];   // zero at rest
__device__ ull g_prefix[Bn];                     // zero at rest
__device__ int g_K[Bn] = {Pn, Pn, Pn, Pn};       // Pn at rest
__device__ int g_candcnt[Bn];                    // zero at rest
__device__ ull g_cand[Bn][Pn];
__device__ volatile unsigned int g_bar[Bn][8];   // zero at rest (reset by gather)

// ---------------------------------------------------------------------------
// 48-bit composite key: (monotone_float32 << 16) | (0xFFFF - idx)
// ---------------------------------------------------------------------------
__device__ __forceinline__ ull make_key(float e, int i) {
    float v = (e < THRESH_F) ? 0.0f : e;
    unsigned int ub = __float_as_uint(v);
    ub = (ub & 0x80000000u) ? ~ub : (ub | 0x80000000u);
    return ((ull)ub << 16) | (ull)(0xFFFFu - (unsigned int)i);
}

// ---------------------------------------------------------------------------
// SM bulk copy: out <- x  (256 MB). float4 grid-stride, 512 CTAs
// (exactly 128 iterations/thread; leaves SM residency for side stream).
// ---------------------------------------------------------------------------
__global__ void __launch_bounds__(256)
copy_kernel(const float4* __restrict__ src, float4* __restrict__ dst) {
    const int n4 = Bn * Cn * HWn / 4;
    int i = blockIdx.x * blockDim.x + threadIdx.x;
    const int stride = gridDim.x * blockDim.x;
    #pragma unroll 4
    for (; i < n4; i += stride) dst[i] = src[i];
}

// ---------------------------------------------------------------------------
// Per-batch global barrier over NBLK blocks (counter + volatile spin).
// ---------------------------------------------------------------------------
#define NBLK 16
__device__ __forceinline__ void batch_barrier(int b, int slot) {
    __threadfence();
    __syncthreads();
    if (threadIdx.x == 0) {
        atomicAdd((unsigned int*)&g_bar[b][slot], 1u);
        while (g_bar[b][slot] < NBLK) { }
        __threadfence();
    }
    __syncthreads();
}

// ---------------------------------------------------------------------------
// Whole top-256 in ONE launch. grid = (NBLK, Bn), 1024 threads.
// Keys live in registers across all 3 radix passes + collect.
// ---------------------------------------------------------------------------
__global__ void __launch_bounds__(1024)
topk_all(const float* __restrict__ edge) {
    const int b   = blockIdx.y;
    const int blk = blockIdx.x;
    const int t   = threadIdx.x;
    const int lane = t & 31;
    const int w    = t >> 5;

    const int ibase = blk * 4096 + t * 4;
    const float4 ev = *(const float4*)&edge[(size_t)b * HWn + ibase];
    ull key[4];
    key[0] = make_key(ev.x, ibase + 0);
    key[1] = make_key(ev.y, ibase + 1);
    key[2] = make_key(ev.z, ibase + 2);
    key[3] = make_key(ev.w, ibase + 3);

    __shared__ unsigned int warpsum[32];
    __shared__ unsigned int warpsuf[32];
    __shared__ int sh_chunk;
    __shared__ unsigned int sh_krem;
    __shared__ unsigned int bins[64];
    __shared__ ull skeys[Pn];

    #pragma unroll
    for (int pass = 2; pass >= 0; --pass) {
        const ull pre = (pass == 2) ? 0ull : *(volatile ull*)&g_prefix[b];
        #pragma unroll
        for (int j = 0; j < 4; ++j) {
            const bool active = (pass == 2) ||
                                ((key[j] >> ((pass + 1) * 16)) == pre);
            const unsigned int bin =
                (unsigned int)((key[j] >> (pass * 16)) & 0xFFFFull);
            const unsigned int amask = __ballot_sync(0xFFFFFFFFu, active);
            if (active) {
                unsigned int peers = __match_any_sync(amask, bin);
                if (lane == __ffs(peers) - 1)
                    atomicAdd(&g_hist[pass][b][bin], (unsigned int)__popc(peers));
                unsigned int peersc = __match_any_sync(amask, bin >> 6);
                if (lane == __ffs(peersc) - 1)
                    atomicAdd(&g_coarse[pass][b][bin >> 6], (unsigned int)__popc(peersc));
            }
        }

        batch_barrier(b, pass * 2);

        if (blk == 0) {
            const unsigned int mine = g_coarse[pass][b][t];
            unsigned int suf = mine;
            #pragma unroll
            for (int off = 1; off < 32; off <<= 1) {
                const unsigned int v = __shfl_down_sync(0xFFFFFFFFu, suf, off);
                if (lane + off < 32) suf += v;
            }
            if (lane == 0) warpsum[w] = suf;
            __syncthreads();

            if (w == 0) {
                const unsigned int ws = warpsum[lane];
                unsigned int wsuf = ws;
                #pragma unroll
                for (int off = 1; off < 32; off <<= 1) {
                    const unsigned int v = __shfl_down_sync(0xFFFFFFFFu, wsuf, off);
                    if (lane + off < 32) wsuf += v;
                }
                warpsuf[lane] = wsuf - ws;
            }
            __syncthreads();

            const unsigned int K = (unsigned int)g_K[b];
            const unsigned int suf_t = suf + warpsuf[w];
            const unsigned int above = suf_t - mine;
            if (suf_t >= K && above < K) {
                sh_chunk = t;
                sh_krem = K - above;
            }
            __syncthreads();

            const int chunk = sh_chunk;
            if (t < 64) bins[t] = g_hist[pass][b][chunk * 64 + t];
            __syncthreads();

            if (w == 0) {
                const unsigned int krem = sh_krem;
                const unsigned int lo = bins[lane];
                const unsigned int hi = bins[lane + 32];

                unsigned int suf_hi = hi;
                #pragma unroll
                for (int off = 1; off < 32; off <<= 1) {
                    const unsigned int v = __shfl_down_sync(0xFFFFFFFFu, suf_hi, off);
                    if (lane + off < 32) suf_hi += v;
                }
                const unsigned int hi_total = __shfl_sync(0xFFFFFFFFu, suf_hi, 0);

                unsigned int suf_lo = lo;
                #pragma unroll
                for (int off = 1; off < 32; off <<= 1) {
                    const unsigned int v = __shfl_down_sync(0xFFFFFFFFu, suf_lo, off);
                    if (lane + off < 32) suf_lo += v;
                }
                suf_lo += hi_total;

                { const unsigned int st = suf_hi, ab = st - hi;
                  if (st >= krem && ab < krem) {
                      g_prefix[b] = (g_prefix[b] << 16) | (ull)(chunk * 64 + 32 + lane);
                      g_K[b] = (int)(krem - ab);
                  } }
                { const unsigned int st = suf_lo, ab = st - lo;
                  if (st >= krem && ab < krem) {
                      g_prefix[b] = (g_prefix[b] << 16) | (ull)(chunk * 64 + lane);
                      g_K[b] = (int)(krem - ab);
                  } }
            }
            __syncthreads();
        }

        batch_barrier(b, pass * 2 + 1);
    }

    const ull cutoff = *(volatile ull*)&g_prefix[b];
    #pragma unroll
    for (int j = 0; j < 4; ++j) {
        if (key[j] >= cutoff) {
            const int p = atomicAdd(&g_candcnt[b], 1);
            if (p < Pn) g_cand[b][p] = key[j];
        }
    }

    batch_barrier(b, 6);

    if (blk == 0) {
        if (t < Pn) skeys[t] = g_cand[b][t];
        __syncthreads();
        for (int kk = 2; kk <= Pn; kk <<= 1) {
            for (int jj = kk >> 1; jj > 0; jj >>= 1) {
                if (t < Pn) {
                    const int ixj = t ^ jj;
                    if (ixj > t) {
                        const ull a = skeys[t];
                        const ull c = skeys[ixj];
                        const bool up = ((t & kk) == 0);
                        if (up ? (a < c) : (a > c)) { skeys[t] = c; skeys[ixj] = a; }
                    }
                }
                __syncthreads();
            }
        }
        if (t < Pn)
            g_idx[b * Pn + t] = (int)(0xFFFFu - (unsigned int)(skeys[t] & 0xFFFFull));
        if (t == 0) {
            g_candcnt[b] = 0;
            g_prefix[b] = 0ull;
            g_K[b] = Pn;
        }
    }

    const int gt = blk * 1024 + t;
    #pragma unroll
    for (int p = 0; p < 3; ++p) {
        #pragma unroll
        for (int r = 0; r < 4; ++r)
            g_hist[p][b][gt + r * 16384] = 0u;
        if (gt < 1024) g_coarse[p][b][gt] = 0u;
    }
    // g_bar reset happens in gather_kernel (strictly after this kernel).
}

// ---------------------------------------------------------------------------
// Gather: feat[b][n][d] = x[b][d][idx[b][n]]   grid (Pn, Bn), 256 threads (d)
// Also resets topk barrier counters for the next graph replay.
// ---------------------------------------------------------------------------
__global__ void gather_kernel(const float* __restrict__ x) {
    const int b = blockIdx.y;
    const int n = blockIdx.x;
    const int d = threadIdx.x;
    if (n == 0 && d < 8) g_bar[b][d] = 0u;
    const int col = g_idx[b * Pn + n];
    g_feat[((b * Pn + n) << 8) + d] =
        x[(size_t)b * Cn * HWn + (size_t)d * HWn + (size_t)col];
}

// ---------------------------------------------------------------------------
// GEMM1 (NN): Z[b,i,d] = relu(BN_adj(sum_j W_adj[i,j]*feat[b,j,d])) + feat[b,i,d]
// 32x64 tile, 256 threads, 2x4 microtile, KB=16.
// grid = (4 d-tiles, 8 i-tiles, Bn) = 128 CTAs.
// ---------------------------------------------------------------------------
__global__ void __launch_bounds__(256)
gemm1_kernel(const float* __restrict__ W,
             const float* __restrict__ ga, const float* __restrict__ ba,
             const float* __restrict__ ma, const float* __restrict__ va) {
    __shared__ __align__(16) float sA[16][36];   // [k][i]  (32 rows + pad)
    __shared__ __align__(16) float sB[16][68];   // [k][d]  (64 cols + pad)

    const int b  = blockIdx.z;
    const float* F = g_feat + b * Pn * Cn;
    float* Z       = g_z    + b * Pn * Cn;
    const int ti = blockIdx.y * 32;
    const int td = blockIdx.x * 64;
    const int t  = threadIdx.x;
    const int tx = t & 15;    // -> 4 cols
    const int ty = t >> 4;    // -> 2 rows

    float acc[2][4] = {};

    for (int k0 = 0; k0 < Pn; k0 += 16) {
        // A: 32x16 = 512 elems, 2 per thread (coalesced 16-wide in k)
        #pragma unroll
        for (int r = 0; r < 2; ++r) {
            const int eI = t + r * 256;
            const int ai = eI >> 4, ak = eI & 15;
            sA[ak][ai] = W[(ti + ai) * Pn + (k0 + ak)];
        }
        // B: 16x64 = 1024 elems, 4 per thread (coalesced 64-wide in d)
        #pragma unroll
        for (int r = 0; r < 4; ++r) {
            const int eI = t + r * 256;
            const int bk = eI >> 6, bd = eI & 63;
            sB[bk][bd] = F[(k0 + bk) * Cn + (td + bd)];
        }
        __syncthreads();
        #pragma unroll
        for (int k = 0; k < 16; ++k) {
            const float a0 = sA[k][ty * 2 + 0];
            const float a1 = sA[k][ty * 2 + 1];
            const float4 b4 = *(const float4*)&sB[k][tx * 4];
            const float br[4] = {b4.x, b4.y, b4.z, b4.w};
            #pragma unroll
            for (int j = 0; j < 4; ++j) {
                acc[0][j] += a0 * br[j];
                acc[1][j] += a1 * br[j];
            }
        }
        __syncthreads();
    }

    #pragma unroll
    for (int ui = 0; ui < 2; ++ui) {
        const int i = ti + ty * 2 + ui;
        const float inv = ga[i] * rsqrtf(va[i] + EPSn);
        const float add = ba[i] - ma[i] * inv;
        #pragma unroll
        for (int ud = 0; ud < 4; ++ud) {
            const int d = td + tx * 4 + ud;
            Z[i * Cn + d] = fmaxf(acc[ui][ud] * inv + add, 0.0f) + F[i * Cn + d];
        }
    }
}

// ---------------------------------------------------------------------------
// GEMM2 (NT): z2[b,p,c] = relu(BN_wg(sum_d Z[b,p,d]*Wg[c,d]))
// 32(p)x64(c) tile, 256 threads, 2x4 microtile, KB=16.
// grid = (4 c-tiles, 8 p-tiles, Bn) = 128 CTAs.
// ---------------------------------------------------------------------------
__global__ void __launch_bounds__(256)
gemm2_kernel(const float* __restrict__ Wg,
             const float* __restrict__ gw, const float* __restrict__ bw,
             const float* __restrict__ mw, const float* __restrict__ vw) {
    __shared__ __align__(16) float sA[16][36];   // [k][p]
    __shared__ __align__(16) float sB[16][68];   // [k][c]

    const int b = blockIdx.z;
    const float* Z = g_z  + b * Pn * Cn;
    float* Z2      = g_z2 + b * Pn * Cn;
    const int tp = blockIdx.y * 32;
    const int tc = blockIdx.x * 64;
    const int t  = threadIdx.x;
    const int tx = t & 15;
    const int ty = t >> 4;

    float acc[2][4] = {};

    for (int k0 = 0; k0 < Cn; k0 += 16) {
        // A: Z rows p, k-major: 32x16, 2/thread (coalesced 16-wide in k)
        #pragma unroll
        for (int r = 0; r < 2; ++r) {
            const int eI = t + r * 256;
            const int ar = eI >> 4, ak = eI & 15;
            sA[ak][ar] = Z[(tp + ar) * Cn + (k0 + ak)];
        }
        // B: Wg rows c, k-major: 64x16, 4/thread (coalesced 16-wide in k)
        #pragma unroll
        for (int r = 0; r < 4; ++r) {
            const int eI = t + r * 256;
            const int br = eI >> 4, bk = eI & 15;
            sB[bk][br] = Wg[(tc + br) * Cn + (k0 + bk)];
        }
        __syncthreads();
        #pragma unroll
        for (int k = 0; k < 16; ++k) {
            const float a0 = sA[k][ty * 2 + 0];
            const float a1 = sA[k][ty * 2 + 1];
            const float4 b4 = *(const float4*)&sB[k][tx * 4];
            const float br4[4] = {b4.x, b4.y, b4.z, b4.w};
            #pragma unroll
            for (int j = 0; j < 4; ++j) {
                acc[0][j] += a0 * br4[j];
                acc[1][j] += a1 * br4[j];
            }
        }
        __syncthreads();
    }

    #pragma unroll
    for (int uc = 0; uc < 4; ++uc) {
        const int c = tc + tx * 4 + uc;
        const float inv = gw[c] * rsqrtf(vw[c] + EPSn);
        const float add = bw[c] - mw[c] * inv;
        #pragma unroll
        for (int ui = 0; ui < 2; ++ui) {
            const int p = tp + ty * 2 + ui;
            Z2[p * Cn + c] = fmaxf(acc[ui][uc] * inv + add, 0.0f);
        }
    }
}

// ---------------------------------------------------------------------------
// Scatter: out[b, c, idx[b,p]] = z2[b,p,c].  grid (Pn, Bn), 256 threads (c).
// ---------------------------------------------------------------------------
__global__ void __launch_bounds__(256)
scatter_kernel(float* __restrict__ out) {
    const int b = blockIdx.y;
    const int p = blockIdx.x;
    const int c = threadIdx.x;
    const int col = g_idx[b * Pn + p];
    out[(size_t)b * Cn * HWn + (size_t)c * HWn + (size_t)col] =
        g_z2[((b * Pn + p) << 8) + c];
}

// ---------------------------------------------------------------------------
extern "C" void kernel_launch(void* const* d_in, const int* in_sizes, int n_in,
                              void* d_out, int out_size) {
    const float* x     = (const float*)d_in[0];
    const float* edge  = (const float*)d_in[1];
    const float* w_adj = (const float*)d_in[2];
    const float* g_adj = (const float*)d_in[3];
    const float* b_adj = (const float*)d_in[4];
    const float* m_adj = (const float*)d_in[5];
    const float* v_adj = (const float*)d_in[6];
    const float* w_wg  = (const float*)d_in[7];
    const float* g_wg  = (const float*)d_in[8];
    const float* b_wg  = (const float*)d_in[9];
    const float* m_wg  = (const float*)d_in[10];
    const float* v_wg  = (const float*)d_in[11];
    float* out = (float*)d_out;

    static cudaStream_t s1 = nullptr;
    static cudaEvent_t evA = nullptr, evB = nullptr;
    if (s1 == nullptr) {
        int lo = 0, hi = 0;
        cudaDeviceGetStreamPriorityRange(&lo, &hi);   // hi = greatest priority
        cudaStreamCreateWithPriority(&s1, cudaStreamNonBlocking, hi);
        cudaEventCreateWithFlags(&evA, cudaEventDisableTiming);
        cudaEventCreateWithFlags(&evB, cudaEventDisableTiming);
    }

    // Fork side stream from stream 0.
    cudaEventRecord(evA, 0);
    cudaStreamWaitEvent(s1, evA, 0);

    // High-priority side stream first: topk -> gather -> GEMMs.
    topk_all<<<dim3(NBLK, Bn), 1024, 0, s1>>>(edge);
    gather_kernel<<<dim3(Pn, Bn), Cn, 0, s1>>>(x);
    gemm1_kernel<<<dim3(4, 8, Bn), 256, 0, s1>>>(w_adj, g_adj, b_adj, m_adj, v_adj);
    gemm2_kernel<<<dim3(4, 8, Bn), 256, 0, s1>>>(w_wg, g_wg, b_wg, m_wg, v_wg);

    // Stream 0: bulk copy x -> out on the SMs (512 CTAs: leaves residency).
    copy_kernel<<<512, 256>>>((const float4*)x, (float4*)out);

    // Join and scatter the reasoned point features into out.
    cudaEventRecord(evB, s1);
    cudaStreamWaitEvent(0, evB, 0);
    scatter_kernel<<<dim3(Pn, Bn), 256>>>(out);
}